// round 16
// baseline (speedup 1.0000x reference)
#include <cuda_runtime.h>

// x[128,3,16,64,64] (*) w[24,3,3,3,3] VALID -> +bias -> min over depth(14) -> softmax over 24ch
// out [128,24,62,62] fp32
//
// Depth-major single-generation loop, 4 fat warps, 4-row x 32-col tiles:
// each thread 6 oc x 4 px (3 oc-pairs, one conflict-free quad). Halved
// per-thread state -> __launch_bounds__(128,4): 4 blocks/SM, 16 warps, and
// grid 4096 -> 6.9 waves (tail loss ~1% vs 8%). Ring rows packed 64 floats
// (no pad; over-reads feed only discarded outputs). f32x2 over (oc,oc+1),
// pixel broadcast via mov.b64 {u,u}, min in registers, one sync per depth.

#define THREADS 128
typedef unsigned long long ull;

__device__ __forceinline__ ull ffma2(ull a, ull b, ull c) {
    ull d;
    asm("fma.rn.f32x2 %0, %1, %2, %3;" : "=l"(d) : "l"(a), "l"(b), "l"(c));
    return d;
}
__device__ __forceinline__ ull min2(ull a, ull b) {
    float alo = __uint_as_float((unsigned)a), ahi = __uint_as_float((unsigned)(a >> 32));
    float blo = __uint_as_float((unsigned)b), bhi = __uint_as_float((unsigned)(b >> 32));
    float lo = fminf(alo, blo), hi = fminf(ahi, bhi);
    return ((ull)__float_as_uint(hi) << 32) | (ull)__float_as_uint(lo);
}
__device__ __forceinline__ ull dup(float v) {
    ull d;
    unsigned u = __float_as_uint(v);
    asm("mov.b64 %0, {%1, %1};" : "=l"(d) : "r"(u));
    return d;
}

// smem layout (floats):
//   wsm  [27 taps][4 ocg][20]       : 2160   (9 pairs = 3kw x 3jp, 2-float pad)
//   ring 4 slots x 1152             : 4608   (3cin x 6row x 64col, packed, no pad)
//   minbuf [128 px][26]             : 3328
#define SM_WSM   0
#define SM_RING  2160
#define SM_MIN   6768
#define SM_TOTAL 10096   // floats = 40384 bytes

// one (cin,kh,kd) tap-row: 18 weight floats (9 pairs) x 6 pixel cols -> 36 FFMA2
__device__ __forceinline__ void body(const float* __restrict__ pr,
                                     const float* __restrict__ wb,
                                     ull (&A)[12])
{
    float4 q  = *(const float4*)pr;
    float2 q2 = *(const float2*)(pr + 4);
    ull pp[6] = { dup(q.x), dup(q.y), dup(q.z), dup(q.w), dup(q2.x), dup(q2.y) };

    ulonglong2 v0 = *(const ulonglong2*)(wb);        // (kw0,jp0) (kw0,jp1)
    ulonglong2 v1 = *(const ulonglong2*)(wb + 4);    // (kw0,jp2) (kw1,jp0)
    ulonglong2 v2 = *(const ulonglong2*)(wb + 8);    // (kw1,jp1) (kw1,jp2)
    ulonglong2 v3 = *(const ulonglong2*)(wb + 12);   // (kw2,jp0) (kw2,jp1)
    ull        v4 = *(const ull*)(wb + 16);          // (kw2,jp2)
    ull w[3][3] = { { v0.x, v0.y, v1.x },
                    { v1.y, v2.x, v2.y },
                    { v3.x, v3.y, v4 } };

    #pragma unroll
    for (int kw = 0; kw < 3; ++kw)
        #pragma unroll
        for (int jp = 0; jp < 3; ++jp)
            #pragma unroll
            for (int px = 0; px < 4; ++px)
                A[jp * 4 + px] = ffma2(w[kw][jp], pp[px + kw], A[jp * 4 + px]);
}

// slice staging as float4: 1152 floats = 288 float4 per slice (full 64-wide rows)
__device__ __forceinline__ void stage_ldg(const float* __restrict__ xb, int r0, int tid,
                                          int s, float4 (&stg)[3]) {
    #pragma unroll
    for (int k = 0; k < 3; ++k) {
        int f = tid + k * THREADS;                 // 0..287 valid
        if (k < 2 || tid < 32) {
            int cin = f / 96, q = f % 96;
            int row = q >> 4, w4 = q & 15;
            int gr = min(r0 + row, 63);
            stg[k] = *(const float4*)(xb + ((cin * 16 + s) << 12) + (gr << 6) + w4 * 4);
        }
    }
}
__device__ __forceinline__ void stage_sts(float* __restrict__ ring, int slot, int tid,
                                          const float4 (&stg)[3]) {
    float* sl = ring + slot * 1152;
    #pragma unroll
    for (int k = 0; k < 3; ++k) {
        int f = tid + k * THREADS;
        if (k < 2 || tid < 32)
            *(float4*)(sl + f * 4) = stg[k];       // packed layout == gmem row order
    }
}

__global__ __launch_bounds__(THREADS, 4)
void conv3d_min_softmax_kernel(const float* __restrict__ x,
                               const float* __restrict__ wgt,
                               const float* __restrict__ bias,
                               float* __restrict__ out)
{
    extern __shared__ float smem[];
    float* wsm    = smem + SM_WSM;
    float* ring   = smem + SM_RING;
    float* minbuf = smem + SM_MIN;

    const int tid = threadIdx.x;
    const int b   = blockIdx.y;
    const int rt  = blockIdx.x >> 1;    // row tile 0..15
    const int wh  = blockIdx.x & 1;     // w half 0..1 (adjacent bx share slices -> L2 hits)
    const int r0  = rt * 4;             // 0..60
    const int wo  = wh * 32;            // 0 or 32

    // ---- stage weights: [tap][ocg][ (kw*3+jp)*2+lane ], stride 20 ----
    for (int i = tid; i < 1944; i += THREADS) {
        int tap = i / 72, rem = i % 72;
        int ocg_ = rem / 18, f = rem % 18;
        int p = f >> 1, lane = f & 1;
        int kw = p / 3, jp = p % 3;
        int oc = ocg_ * 6 + jp * 2 + lane;
        wsm[(tap * 4 + ocg_) * 20 + p * 2 + lane] = wgt[oc * 81 + tap * 3 + kw];
    }

    const float* xb = x + (size_t)b * (3 * 16 * 4096);
    float4 stg[3];

    // prologue: slices 0,1 to slots 0,1; prefetch slice 2
    stage_ldg(xb, r0, tid, 0, stg); stage_sts(ring, 0, tid, stg);
    stage_ldg(xb, r0, tid, 1, stg); stage_sts(ring, 1, tid, stg);
    stage_ldg(xb, r0, tid, 2, stg);

    const int ocg = tid >> 5;            // 0..3, warp-uniform -> weight broadcast
    const int g   = tid & 31;
    const int r   = g >> 3;              // tile row 0..3
    const int wq  = wo + (g & 7) * 4;    // quad base col in ring row
    const int oc0 = ocg * 6;

    ull bini[3];
    #pragma unroll
    for (int jp = 0; jp < 3; ++jp)
        bini[jp] = *(const ull*)(bias + oc0 + 2 * jp);

    ull A[12];
    #pragma unroll
    for (int t = 0; t < 12; ++t) A[t] = bini[t >> 2];

    const ull INF2 = 0x7F8000007F800000ULL;
    ull mn[12];
    #pragma unroll
    for (int t = 0; t < 12; ++t) mn[t] = INF2;

    #pragma unroll 1
    for (int d = 0; d < 14; ++d) {
        // slot (d+2)&3 held slice d-2 (last read in iteration d-2; iteration
        // d-1's barrier ordered those reads before this store)
        stage_sts(ring, (d + 2) & 3, tid, stg);
        if (d + 3 <= 15) stage_ldg(xb, r0, tid, d + 3, stg);
        __syncthreads();

        const float* s0 = ring + ((d    ) & 3) * 1152;
        const float* s1 = ring + ((d + 1) & 3) * 1152;
        const float* s2 = ring + ((d + 2) & 3) * 1152;

        #pragma unroll 3
        for (int ck = 0; ck < 9; ++ck) {           // ck = cin*3 + kh
            int cin = ck / 3, kh = ck % 3;
            int rowoff = (cin * 6 + r + kh) * 64 + wq;
            const float* wt = wsm + ((cin * 9 + kh) * 4 + ocg) * 20;   // kd=0 tap
            body(s0 + rowoff, wt,       A);        // kd=0
            body(s1 + rowoff, wt + 240, A);        // kd=1 (+3 taps * 80)
            body(s2 + rowoff, wt + 480, A);        // kd=2
        }

        #pragma unroll
        for (int t = 0; t < 12; ++t) {
            mn[t] = min2(mn[t], A[t]);
            A[t] = bini[t >> 2];
        }
    }

    // ---- write per-thread mins to smem (128 local pixels) ----
    #pragma unroll
    for (int jp = 0; jp < 3; ++jp)
        #pragma unroll
        for (int px = 0; px < 4; ++px) {
            int pix = r * 32 + (g & 7) * 4 + px;
            *(ull*)(minbuf + pix * 26 + oc0 + 2 * jp) = mn[jp * 4 + px];
        }
    __syncthreads();

    // ---- softmax over 24 channels per pixel (128 pixels, 1/thread) ----
    {
        float* row = minbuf + tid * 26;
        float m = -3.402823466e38f;
        #pragma unroll
        for (int oc = 0; oc < 24; ++oc) m = fmaxf(m, row[oc]);
        float ssum = 0.f;
        #pragma unroll
        for (int oc = 0; oc < 24; ++oc) {
            float e = __expf(row[oc] - m);
            row[oc] = e;
            ssum += e;
        }
        float rinv = 1.0f / ssum;
        #pragma unroll
        for (int oc = 0; oc < 24; ++oc) row[oc] *= rinv;
    }
    __syncthreads();

    // ---- coalesced store ----
    float* ob = out + (size_t)b * (24 * 62 * 62);
    for (int i = tid; i < 24 * 128; i += THREADS) {
        int oc = i >> 7, pix = i & 127;
        int lrow = pix >> 5, lw = pix & 31;
        int oh = r0 + lrow, w = wo + lw;
        if (w < 62 && oh < 62)
            ob[(oc * 62 + oh) * 62 + w] = minbuf[pix * 26 + oc];
    }
}

extern "C" void kernel_launch(void* const* d_in, const int* in_sizes, int n_in,
                              void* d_out, int out_size) {
    const float* x    = (const float*)d_in[0];
    const float* wgt  = (const float*)d_in[1];
    const float* bias = (const float*)d_in[2];
    float* out = (float*)d_out;

    cudaFuncSetAttribute(conv3d_min_softmax_kernel,
                         cudaFuncAttributeMaxDynamicSharedMemorySize,
                         SM_TOTAL * (int)sizeof(float));
    dim3 grid(32, 128);   // (16 row-tiles x 2 w-halves) x 128 batches
    conv3d_min_softmax_kernel<<<grid, THREADS, SM_TOTAL * sizeof(float)>>>(x, wgt, bias, out);
}

// round 17
// speedup vs baseline: 1.7220x; 1.7220x over previous
#include <cuda_runtime.h>

// x[128,3,16,64,64] (*) w[24,3,3,3,3] VALID -> +bias -> min over depth(14) -> softmax over 24ch
// out [128,24,62,62] fp32
//
// R15 structure (469us): depth-major single-generation loop, 4 fat warps,
// 4-row x 64-col tiles, 6 oc x 8 px per thread, f32x2 over (oc,oc+1),
// pixel broadcast via mov.b64 {u,u}, min in registers, unroll 3, (128,3).
// This round: slice staging via cp.async (LDGSTS) -- no register roundtrip,
// no STS on the LDS crossbar, copy of slice d+3 overlaps compute of depth d.

#define THREADS 128
typedef unsigned long long ull;

__device__ __forceinline__ ull ffma2(ull a, ull b, ull c) {
    ull d;
    asm("fma.rn.f32x2 %0, %1, %2, %3;" : "=l"(d) : "l"(a), "l"(b), "l"(c));
    return d;
}
__device__ __forceinline__ ull min2(ull a, ull b) {
    float alo = __uint_as_float((unsigned)a), ahi = __uint_as_float((unsigned)(a >> 32));
    float blo = __uint_as_float((unsigned)b), bhi = __uint_as_float((unsigned)(b >> 32));
    float lo = fminf(alo, blo), hi = fminf(ahi, bhi);
    return ((ull)__float_as_uint(hi) << 32) | (ull)__float_as_uint(lo);
}
__device__ __forceinline__ ull dup(float v) {
    ull d;
    unsigned u = __float_as_uint(v);
    asm("mov.b64 %0, {%1, %1};" : "=l"(d) : "r"(u));
    return d;
}
__device__ __forceinline__ void cp_async16(unsigned saddr, const void* gaddr) {
    asm volatile("cp.async.ca.shared.global [%0], [%1], 16;" :: "r"(saddr), "l"(gaddr));
}

// smem layout (floats):
//   wsm  [27 taps][4 ocg][20]        : 2160   (9 pairs = 3kw x 3jp, 2-float pad)
//   ring 4 slots x [18 rows][68]     : 4896   (3cin x 6row, plain pixels, 4-col pad)
//   minbuf [256 px][26]              : 6656
#define SM_WSM   0
#define SM_RING  2160
#define SM_MIN   7056
#define SM_TOTAL 13712   // floats = 54848 bytes

// one (cin,kh,kd) tap-row: 18 weight floats (9 pairs) x 12 pixels -> 72 FFMA2
__device__ __forceinline__ void body(const float* __restrict__ pr,
                                     const float* __restrict__ wb,
                                     ull (&A)[24])
{
    float4 q  = *(const float4*)pr;
    float2 q2 = *(const float2*)(pr + 4);
    ull ppA[6] = { dup(q.x), dup(q.y), dup(q.z), dup(q.w), dup(q2.x), dup(q2.y) };
    float4 s  = *(const float4*)(pr + 32);
    float2 s2 = *(const float2*)(pr + 36);
    ull ppB[6] = { dup(s.x), dup(s.y), dup(s.z), dup(s.w), dup(s2.x), dup(s2.y) };

    ulonglong2 v0 = *(const ulonglong2*)(wb);        // (kw0,jp0) (kw0,jp1)
    ulonglong2 v1 = *(const ulonglong2*)(wb + 4);    // (kw0,jp2) (kw1,jp0)
    ulonglong2 v2 = *(const ulonglong2*)(wb + 8);    // (kw1,jp1) (kw1,jp2)
    ulonglong2 v3 = *(const ulonglong2*)(wb + 12);   // (kw2,jp0) (kw2,jp1)
    ull        v4 = *(const ull*)(wb + 16);          // (kw2,jp2)
    ull w[3][3] = { { v0.x, v0.y, v1.x },
                    { v1.y, v2.x, v2.y },
                    { v3.x, v3.y, v4 } };

    #pragma unroll
    for (int kw = 0; kw < 3; ++kw)
        #pragma unroll
        for (int jp = 0; jp < 3; ++jp) {
            #pragma unroll
            for (int px = 0; px < 4; ++px)
                A[jp * 8 + px]     = ffma2(w[kw][jp], ppA[px + kw], A[jp * 8 + px]);
            #pragma unroll
            for (int px = 0; px < 4; ++px)
                A[jp * 8 + 4 + px] = ffma2(w[kw][jp], ppB[px + kw], A[jp * 8 + 4 + px]);
        }
}

// async slice staging: 288 x 16B copies, gmem -> ring slot, no registers
__device__ __forceinline__ void stage_async(const float* __restrict__ xb,
                                            unsigned ring_u32, int slot,
                                            int r0, int tid, int s)
{
    unsigned sl = ring_u32 + (unsigned)(slot * 1224) * 4u;
    #pragma unroll
    for (int k = 0; k < 3; ++k) {
        int f = tid + k * THREADS;                 // 0..287 valid
        if (k < 2 || tid < 32) {
            int cin = f / 96, q = f % 96;
            int row = q >> 4, w4 = q & 15;
            int gr = min(r0 + row, 63);
            cp_async16(sl + (unsigned)((cin * 6 + row) * 68 + w4 * 4) * 4u,
                       xb + ((cin * 16 + s) << 12) + (gr << 6) + w4 * 4);
        }
    }
    asm volatile("cp.async.commit_group;" ::: "memory");
}

__global__ __launch_bounds__(THREADS, 3)
void conv3d_min_softmax_kernel(const float* __restrict__ x,
                               const float* __restrict__ wgt,
                               const float* __restrict__ bias,
                               float* __restrict__ out)
{
    extern __shared__ float smem[];
    float* wsm    = smem + SM_WSM;
    float* ring   = smem + SM_RING;
    float* minbuf = smem + SM_MIN;
    const unsigned ring_u32 = (unsigned)__cvta_generic_to_shared(ring);

    const int tid = threadIdx.x;
    const int b   = blockIdx.y;
    const int r0  = blockIdx.x * 4;     // 0..60

    // ---- stage weights: [tap][ocg][ (kw*3+jp)*2+lane ], stride 20 ----
    for (int i = tid; i < 1944; i += THREADS) {
        int tap = i / 72, rem = i % 72;
        int ocg_ = rem / 18, f = rem % 18;
        int p = f >> 1, lane = f & 1;
        int kw = p / 3, jp = p % 3;
        int oc = ocg_ * 6 + jp * 2 + lane;
        wsm[(tap * 4 + ocg_) * 20 + p * 2 + lane] = wgt[oc * 81 + tap * 3 + kw];
    }
    // zero image pads (cols 64..67 of each row, all 4 slots)
    for (int i = tid; i < 288; i += THREADS) {
        int slot = i / 72, rem = i % 72;
        int row = rem >> 2, c = rem & 3;
        ring[slot * 1224 + row * 68 + 64 + c] = 0.f;
    }

    const float* xb = x + (size_t)b * (3 * 16 * 4096);

    // prologue: async-copy slices 0,1,2 into slots 0,1,2
    stage_async(xb, ring_u32, 0, r0, tid, 0);
    stage_async(xb, ring_u32, 1, r0, tid, 1);
    stage_async(xb, ring_u32, 2, r0, tid, 2);

    const int ocg = tid >> 5;            // 0..3, warp-uniform -> weight broadcast
    const int g   = tid & 31;
    const int r   = g >> 3;              // tile row 0..3
    const int w0  = (g & 7) * 4;         // quad A at w0, quad B at w0+32
    const int oc0 = ocg * 6;

    ull bini[3];
    #pragma unroll
    for (int jp = 0; jp < 3; ++jp)
        bini[jp] = *(const ull*)(bias + oc0 + 2 * jp);

    ull A[24];
    #pragma unroll
    for (int t = 0; t < 24; ++t) A[t] = bini[t >> 3];

    const ull INF2 = 0x7F8000007F800000ULL;
    ull mn[24];
    #pragma unroll
    for (int t = 0; t < 24; ++t) mn[t] = INF2;

    #pragma unroll 1
    for (int d = 0; d < 14; ++d) {
        // all outstanding copies (through slice d+2) complete, then block-wide
        // visibility + end of iter d-1 reads
        asm volatile("cp.async.wait_group 0;" ::: "memory");
        __syncthreads();
        // issue copy of slice d+3 into slot (d+3)&3 = (d-1)&3 (its last reads
        // ended in iter d-1, ordered by the barrier above); overlaps compute
        if (d + 3 <= 15) stage_async(xb, ring_u32, (d + 3) & 3, r0, tid, d + 3);

        const float* s0 = ring + ((d    ) & 3) * 1224;
        const float* s1 = ring + ((d + 1) & 3) * 1224;
        const float* s2 = ring + ((d + 2) & 3) * 1224;

        #pragma unroll 3
        for (int ck = 0; ck < 9; ++ck) {           // ck = cin*3 + kh
            int cin = ck / 3, kh = ck % 3;
            int rowoff = (cin * 6 + r + kh) * 68 + w0;
            const float* wt = wsm + ((cin * 9 + kh) * 4 + ocg) * 20;   // kd=0 tap
            body(s0 + rowoff, wt,       A);        // kd=0
            body(s1 + rowoff, wt + 240, A);        // kd=1 (+3 taps * 80)
            body(s2 + rowoff, wt + 480, A);        // kd=2
        }

        #pragma unroll
        for (int t = 0; t < 24; ++t) {
            mn[t] = min2(mn[t], A[t]);
            A[t] = bini[t >> 3];
        }
    }

    // ---- write per-thread mins to smem ----
    #pragma unroll
    for (int jp = 0; jp < 3; ++jp)
        #pragma unroll
        for (int hf = 0; hf < 2; ++hf)
            #pragma unroll
            for (int px = 0; px < 4; ++px) {
                int pix = r * 64 + hf * 32 + w0 + px;
                *(ull*)(minbuf + pix * 26 + oc0 + 2 * jp) = mn[jp * 8 + hf * 4 + px];
            }
    __syncthreads();

    // ---- softmax over 24 channels per pixel (256 pixels) ----
    for (int p = tid; p < 256; p += THREADS) {
        float* row = minbuf + p * 26;
        float m = -3.402823466e38f;
        #pragma unroll
        for (int oc = 0; oc < 24; ++oc) m = fmaxf(m, row[oc]);
        float ssum = 0.f;
        #pragma unroll
        for (int oc = 0; oc < 24; ++oc) {
            float e = __expf(row[oc] - m);
            row[oc] = e;
            ssum += e;
        }
        float rinv = 1.0f / ssum;
        #pragma unroll
        for (int oc = 0; oc < 24; ++oc) row[oc] *= rinv;
    }
    __syncthreads();

    // ---- coalesced store ----
    float* ob = out + (size_t)b * (24 * 62 * 62);
    for (int i = tid; i < 24 * 256; i += THREADS) {
        int oc = i / 256, pix = i & 255;
        int row = pix >> 6, w = pix & 63;
        int oh = r0 + row;
        if (w < 62 && oh < 62)
            ob[(oc * 62 + oh) * 62 + w] = minbuf[pix * 26 + oc];
    }
}

extern "C" void kernel_launch(void* const* d_in, const int* in_sizes, int n_in,
                              void* d_out, int out_size) {
    const float* x    = (const float*)d_in[0];
    const float* wgt  = (const float*)d_in[1];
    const float* bias = (const float*)d_in[2];
    float* out = (float*)d_out;

    cudaFuncSetAttribute(conv3d_min_softmax_kernel,
                         cudaFuncAttributeMaxDynamicSharedMemorySize,
                         SM_TOTAL * (int)sizeof(float));
    dim3 grid(16, 128);   // 16 four-row tiles x 128 batches
    conv3d_min_softmax_kernel<<<grid, THREADS, SM_TOTAL * sizeof(float)>>>(x, wgt, bias, out);
}